// round 11
// baseline (speedup 1.0000x reference)
#include <cuda_runtime.h>
#include <cuda_fp16.h>
#include <mma.h>

using namespace nvcuda;

#define NN 50000
#define NE 800000
#define NG 1024
#define DIN 9
#define DD 64
#define SCAN_BLKS ((NN + 255) / 256)   // 196
#define GMN 64                          // nodes per gemm64 block
#define EPAD (NE + 4*NN)                // padded edge array size

// ---- scratch (static device globals) ----
__device__ __half2  g_h2 [NN*32];        // activations (post-tanh), fp16
__device__ __half2  g_z2 [(NN+1)*32];    // z = dinv * (h @ W), fp16; row NN = 0
__device__ float    g_zx [(NN+1)*16];    // dinv * x, padded to 16; row NN = 0
__device__ float    g_aggx[NN*DIN];      // layer-0 aggregate
__device__ int      g_degi[NN];          // in-degree (no self loop)
__device__ float    g_dinv[NN];
__device__ int      g_rp  [NN];          // padded CSR row start (4-aligned)
__device__ int      g_cur [NN];          // fill cursor (pre-seeded with rp)
__device__ int      g_es  [EPAD];        // src indices, padded rows -> NN
__device__ int      g_bsum[256];
__device__ int4     g_dummyq = {NN, NN, NN, NN};
__device__ unsigned g_gmax[NG*DD];
__device__ float    g_gsum[NG*DD];
__device__ float    g_gcnt[NG];

__device__ __forceinline__ unsigned fkey(float f) {
    unsigned b = __float_as_uint(f);
    return (b & 0x80000000u) ? ~b : (b | 0x80000000u);
}
__device__ __forceinline__ float funkey(unsigned k) {
    unsigned b = (k & 0x80000000u) ? (k & 0x7FFFFFFFu) : ~k;
    return __uint_as_float(b);
}

__global__ void k_init() {
    int i = blockIdx.x * blockDim.x + threadIdx.x;
    if (i < NN) g_degi[i] = 0;
    if (i < NG*DD) { g_gmax[i] = 0u; g_gsum[i] = 0.0f; }
    if (i < NG) g_gcnt[i] = 0.0f;
    if (i < 32) g_z2[NN*32 + i] = __float2half2_rn(0.0f);   // dummy z row
    if (i < 16) g_zx[NN*16 + i] = 0.0f;                     // dummy zx row
}

__global__ void k_deg(const int4* __restrict__ dst4) {
    int e = blockIdx.x * blockDim.x + threadIdx.x;
    if (e >= NE/4) return;
    int4 d = dst4[e];
    atomicAdd(&g_degi[d.x], 1);
    atomicAdd(&g_degi[d.y], 1);
    atomicAdd(&g_degi[d.z], 1);
    atomicAdd(&g_degi[d.w], 1);
}

// shuffle scan of PADDED degree -> rp (exclusive), block sums
__global__ void k_scan1() {
    __shared__ int wsum[8], wpre[8];
    int t = threadIdx.x, i = blockIdx.x * 256 + t;
    int lane = t & 31, w = t >> 5;
    int v = (i < NN) ? ((g_degi[i] + 3) & ~3) : 0;
    int s = v;
    #pragma unroll
    for (int off = 1; off < 32; off <<= 1) {
        int u = __shfl_up_sync(0xFFFFFFFFu, s, off);
        if (lane >= off) s += u;
    }
    if (lane == 31) wsum[w] = s;
    __syncthreads();
    if (t == 0) {
        int a = 0;
        #pragma unroll
        for (int j = 0; j < 8; j++) { wpre[j] = a; a += wsum[j]; }
    }
    __syncthreads();
    int incl = s + wpre[w];
    if (i < NN) g_rp[i] = incl - v;
    if (t == 255) g_bsum[blockIdx.x] = incl;
}

// re-scan bsum + apply; cursor=rp, dinv, pad-slot fill (zx moved out)
__global__ void k_scan3() {
    __shared__ int wsum[8], wpre[8], allincl[256];
    int t = threadIdx.x;
    int lane = t & 31, w = t >> 5;
    int v = (t < SCAN_BLKS) ? g_bsum[t] : 0;
    int s = v;
    #pragma unroll
    for (int off = 1; off < 32; off <<= 1) {
        int u = __shfl_up_sync(0xFFFFFFFFu, s, off);
        if (lane >= off) s += u;
    }
    if (lane == 31) wsum[w] = s;
    __syncthreads();
    if (t == 0) {
        int a = 0;
        #pragma unroll
        for (int j = 0; j < 8; j++) { wpre[j] = a; a += wsum[j]; }
    }
    __syncthreads();
    allincl[t] = s + wpre[w];
    __syncthreads();
    int boff = (blockIdx.x > 0) ? allincl[blockIdx.x - 1] : 0;
    int i = blockIdx.x * 256 + t;
    if (i < NN) {
        int rp = g_rp[i] + boff;
        g_rp[i] = rp;
        g_cur[i] = rp;                               // cursor starts at row base
        int dg = g_degi[i];
        g_dinv[i] = rsqrtf(1.0f + (float)dg);
        int pdg = (dg + 3) & ~3;
        for (int p = dg; p < pdg; p++) g_es[rp + p] = NN;   // pad -> dummy node
    }
}

// coalesced zx = dinv * x (padded to 16 floats/row)
__global__ void k_zx(const float* __restrict__ x) {
    int t = blockIdx.x * blockDim.x + threadIdx.x;
    if (t >= NN*16) return;
    int n = t >> 4, k = t & 15;
    float v = (k < DIN) ? g_dinv[n] * x[n*DIN + k] : 0.0f;
    g_zx[t] = v;
}

// 2 int4s per thread: 8 independent atomic->store chains; cur pre-seeded with rp
__global__ void k_fill(const int4* __restrict__ src4, const int4* __restrict__ dst4) {
    int e = blockIdx.x * blockDim.x + threadIdx.x;
    if (e >= NE/8) return;
    int4 s0 = src4[2*e], d0 = dst4[2*e];
    int4 s1 = src4[2*e+1], d1 = dst4[2*e+1];
    g_es[atomicAdd(&g_cur[d0.x], 1)] = s0.x;
    g_es[atomicAdd(&g_cur[d0.y], 1)] = s0.y;
    g_es[atomicAdd(&g_cur[d0.z], 1)] = s0.z;
    g_es[atomicAdd(&g_cur[d0.w], 1)] = s0.w;
    g_es[atomicAdd(&g_cur[d1.x], 1)] = s1.x;
    g_es[atomicAdd(&g_cur[d1.y], 1)] = s1.y;
    g_es[atomicAdd(&g_cur[d1.z], 1)] = s1.z;
    g_es[atomicAdd(&g_cur[d1.w], 1)] = s1.w;
}

// layer-0: 2 nodes/warp (16 lanes each), clamped uniform loop (no divergence)
__global__ void k_gather9() {
    int t = blockIdx.x * blockDim.x + threadIdx.x;
    int w = t >> 5, lane = t & 31;
    int n = w*2 + (lane >> 4);            // NN even -> both nodes valid
    int c = lane & 15;
    if (n >= NN) return;
    int rp = g_rp[n];
    int q = ((g_degi[n] + 3) & ~3) >> 2;
    int qmax = __reduce_max_sync(0xFFFFFFFFu, q);
    float a0 = g_zx[n*16 + c], a1 = 0.0f;
    const int4* sp = reinterpret_cast<const int4*>(&g_es[rp]);
    for (int it = 0; it < qmax; it++) {
        const int4* p = (it < q) ? (sp + it) : &g_dummyq;
        int4 s = *p;
        a0 += g_zx[s.x*16 + c];
        a1 += g_zx[s.y*16 + c];
        a0 += g_zx[s.z*16 + c];
        a1 += g_zx[s.w*16 + c];
    }
    if (c < DIN) g_aggx[n*DIN + c] = g_dinv[n] * (a0 + a1);
}

// h0 = tanh(aggx @ W0 + b0) -> fp16; 8 nodes/block, lane computes 2 cols
__global__ void k_gemm0f(const float* __restrict__ W, const float* __restrict__ b) {
    __shared__ float Ws[DIN*DD];
    __shared__ float axs[8][DIN];
    int tid = threadIdx.x;
    for (int i = tid; i < DIN*DD; i += 256) Ws[i] = W[i];
    int nb = blockIdx.x * 8;
    if (tid < 8*DIN) {
        int r = tid / DIN, k = tid % DIN, n = nb + r;
        axs[r][k] = (n < NN) ? g_aggx[n*DIN + k] : 0.0f;
    }
    __syncthreads();
    int r = tid >> 5, l = tid & 31;
    int n = nb + r;
    if (n >= NN) return;
    int c0 = 2*l, c1 = 2*l + 1;
    float s0 = b[c0], s1 = b[c1];
    #pragma unroll
    for (int k = 0; k < DIN; k++) {
        float a = axs[r][k];
        s0 += a * Ws[k*DD + c0];
        s1 += a * Ws[k*DD + c1];
    }
    g_h2[n*32 + l] = __floats2half2_rn(tanhf(s0), tanhf(s1));
}

// z = dinv * (h @ W) via tensor cores: fp16 in, fp32 acc, fp16 out.
#define HP 72   // Hs/Wsh pitch in halfs (mult of 8)
__global__ void k_gemm64(const float* __restrict__ W) {
    __shared__ __half Hs [GMN][HP];
    __shared__ __half Wsh[DD ][HP];
    __shared__ float  stage[8][16][20];
    int tid = threadIdx.x;
    int wid = tid >> 5, lane = tid & 31;
    int nb = blockIdx.x * GMN;

    #pragma unroll
    for (int i = 0; i < 4; i++) {
        int idx = tid + i*256;
        float4 f = reinterpret_cast<const float4*>(W)[idx];
        int r = idx >> 4, c0 = (idx & 15) * 4;
        __half2 p0 = __floats2half2_rn(f.x, f.y);
        __half2 p1 = __floats2half2_rn(f.z, f.w);
        *reinterpret_cast<__half2*>(&Wsh[r][c0])     = p0;
        *reinterpret_cast<__half2*>(&Wsh[r][c0 + 2]) = p1;
    }
    #pragma unroll
    for (int i = 0; i < 2; i++) {
        int idx = tid + i*256;
        int n = idx >> 3, q = idx & 7;
        int gn = nb + n;
        uint4 v = make_uint4(0u, 0u, 0u, 0u);
        if (gn < NN) v = reinterpret_cast<const uint4*>(g_h2)[gn*8 + q];
        *reinterpret_cast<uint4*>(&Hs[n][q*8]) = v;
    }
    __syncthreads();

    wmma::fragment<wmma::matrix_a, 16, 16, 16, __half, wmma::row_major> fa;
    wmma::fragment<wmma::matrix_b, 16, 16, 16, __half, wmma::row_major> fb;

    #pragma unroll
    for (int tt = 0; tt < 2; tt++) {
        int t = wid + tt*8;
        int tr = t >> 2, tc = t & 3;
        wmma::fragment<wmma::accumulator, 16, 16, 16, float> fc;
        wmma::fill_fragment(fc, 0.0f);
        #pragma unroll
        for (int k0 = 0; k0 < 4; k0++) {
            wmma::load_matrix_sync(fa, &Hs[tr*16][k0*16], HP);
            wmma::load_matrix_sync(fb, &Wsh[k0*16][tc*16], HP);
            wmma::mma_sync(fc, fa, fb, fc);
        }
        wmma::store_matrix_sync(&stage[wid][0][0], fc, 20, wmma::mem_row_major);
        __syncwarp();
        #pragma unroll
        for (int e = 0; e < 4; e++) {
            int idx = lane + e*32;
            int r = idx >> 3, c2 = idx & 7;
            int gn = nb + tr*16 + r;
            if (gn < NN) {
                float dv = g_dinv[gn];
                float f0 = stage[wid][r][c2*2];
                float f1 = stage[wid][r][c2*2 + 1];
                g_z2[gn*32 + tc*8 + c2] = __floats2half2_rn(dv*f0, dv*f1);
            }
        }
        __syncwarp();
    }
}

__device__ __forceinline__ void quad_acc(int4 q, int lane, float& ax, float& ay) {
    __half2 h0 = g_z2[q.x*32 + lane];
    __half2 h1 = g_z2[q.y*32 + lane];
    __half2 h2 = g_z2[q.z*32 + lane];
    __half2 h3 = g_z2[q.w*32 + lane];
    __half2 sA = __hadd2(__hadd2(h0, h1), __hadd2(h2, h3));
    float2 fA = __half22float2(sA);
    ax += fA.x;
    ay += fA.y;
}

// gather: 2 nodes per warp, independent chains, warp-uniform guards
template <bool POOL>
__global__ void k_gather64(const float* __restrict__ b, const int* __restrict__ batch) {
    int w = (blockIdx.x * blockDim.x + threadIdx.x) >> 5;
    int lane = threadIdx.x & 31;
    int n0 = 2*w, n1 = n0 + 1;
    if (n0 >= NN) return;                 // NN even -> n1 valid whenever n0 is
    int rp0 = g_rp[n0], q0 = ((g_degi[n0] + 3) & ~3) >> 2;
    int rp1 = g_rp[n1], q1 = ((g_degi[n1] + 3) & ~3) >> 2;
    float2 s0 = __half22float2(g_z2[n0*32 + lane]);
    float2 s1 = __half22float2(g_z2[n1*32 + lane]);
    float ax0 = s0.x, ay0 = s0.y;
    float ax1 = s1.x, ay1 = s1.y;
    const int4* sp0 = reinterpret_cast<const int4*>(&g_es[rp0]);
    const int4* sp1 = reinterpret_cast<const int4*>(&g_es[rp1]);
    int iters = max(q0, q1);
    for (int it = 0; it < iters; it++) {
        if (it < q0) quad_acc(sp0[it], lane, ax0, ay0);
        if (it < q1) quad_acc(sp1[it], lane, ax1, ay1);
    }
    float2 bb = reinterpret_cast<const float2*>(b)[lane];
    float dv0 = g_dinv[n0], dv1 = g_dinv[n1];
    float rx0 = tanhf(dv0*ax0 + bb.x);
    float ry0 = tanhf(dv0*ay0 + bb.y);
    float rx1 = tanhf(dv1*ax1 + bb.x);
    float ry1 = tanhf(dv1*ay1 + bb.y);
    g_h2[n0*32 + lane] = __floats2half2_rn(rx0, ry0);
    g_h2[n1*32 + lane] = __floats2half2_rn(rx1, ry1);
    if (POOL) {
        int g0 = batch[n0];
        int base0 = g0*DD + 2*lane;
        atomicMax(&g_gmax[base0 + 0], fkey(rx0));
        atomicMax(&g_gmax[base0 + 1], fkey(ry0));
        atomicAdd(&g_gsum[base0 + 0], rx0);
        atomicAdd(&g_gsum[base0 + 1], ry0);
        int g1 = batch[n1];
        int base1 = g1*DD + 2*lane;
        atomicMax(&g_gmax[base1 + 0], fkey(rx1));
        atomicMax(&g_gmax[base1 + 1], fkey(ry1));
        atomicAdd(&g_gsum[base1 + 0], rx1);
        atomicAdd(&g_gsum[base1 + 1], ry1);
        if (lane == 0) { atomicAdd(&g_gcnt[g0], 1.0f); atomicAdd(&g_gcnt[g1], 1.0f); }
    }
}

// warp-per-graph output head
__global__ void k_out(const float* __restrict__ Wout, const float* __restrict__ bout,
                      float* __restrict__ out) {
    int g = (blockIdx.x * blockDim.x + threadIdx.x) >> 5;
    int lane = threadIdx.x & 31;
    if (g >= NG) return;
    float cnt = fmaxf(g_gcnt[g], 1.0f);
    float s = 0.0f;
    #pragma unroll
    for (int d = lane; d < DD; d += 32) {
        s += funkey(g_gmax[g*DD + d]) * Wout[d]
           + (g_gsum[g*DD + d] / cnt) * Wout[DD + d];
    }
    #pragma unroll
    for (int o = 16; o > 0; o >>= 1) s += __shfl_down_sync(0xFFFFFFFFu, s, o);
    if (lane == 0) out[g] = s + bout[0];
}

extern "C" void kernel_launch(void* const* d_in, const int* in_sizes, int n_in,
                              void* d_out, int out_size) {
    const float* x     = (const float*)d_in[0];
    const int*   eidx  = (const int*)  d_in[1];
    const int*   batch = (const int*)  d_in[2];
    const float* W0 = (const float*)d_in[3];  const float* b0 = (const float*)d_in[4];
    const float* W1 = (const float*)d_in[5];  const float* b1 = (const float*)d_in[6];
    const float* W2 = (const float*)d_in[7];  const float* b2 = (const float*)d_in[8];
    const float* W3 = (const float*)d_in[9];  const float* b3 = (const float*)d_in[10];
    const float* Wout = (const float*)d_in[11];
    const float* bout = (const float*)d_in[12];
    float* out = (float*)d_out;

    const int* src = eidx;
    const int* dst = eidx + NE;

    // ---- CSR build (padded rows, index-only edges) ----
    k_init <<<(NG*DD + 255) / 256, 256>>>();
    k_deg  <<<(NE/4 + 255) / 256, 256>>>((const int4*)dst);
    k_scan1<<<SCAN_BLKS, 256>>>();
    k_scan3<<<SCAN_BLKS, 256>>>();
    k_zx   <<<(NN*16 + 255) / 256, 256>>>(x);
    k_fill <<<(NE/8 + 255) / 256, 256>>>((const int4*)src, (const int4*)dst);

    const int gw_blocks = (NN/2*32 + 255) / 256;   // 3125 (2 nodes per warp)
    const int gm_blocks = (NN + GMN - 1) / GMN;    // 782

    // layer 0
    k_gather9<<<gw_blocks, 256>>>();
    k_gemm0f <<<(NN + 7) / 8, 256>>>(W0, b0);
    // layers 1-3
    k_gemm64  <<<gm_blocks, 256>>>(W1);
    k_gather64<false><<<gw_blocks, 256>>>(b1, batch);
    k_gemm64  <<<gm_blocks, 256>>>(W2);
    k_gather64<false><<<gw_blocks, 256>>>(b2, batch);
    k_gemm64  <<<gm_blocks, 256>>>(W3);
    k_gather64<true> <<<gw_blocks, 256>>>(b3, batch);

    k_out<<<(NG*32 + 255) / 256, 256>>>(Wout, bout, out);
}